// round 2
// baseline (speedup 1.0000x reference)
#include <cuda_runtime.h>
#include <cstdint>

// DisparityWarping, two-kernel split:
//  K1 (mask): per-row occlusion scatter-max + in-bounds test -> mask plane.
//  K2 (warp): barrier-free bilinear gather, 4 channels per thread to keep the
//             per-thread LDG burst small (MLP_p1 ~16 instead of 64).
//
// Grid arithmetic replicates the JAX reference op-for-op (__fdiv_rn, same
// associativity) so floor/boundary decisions match bit-for-bit.

#define H 320
#define W 1024
#define C 16
#define NB 4
#define HW (H * W)
#define CHW (C * HW)

#define CPG 4                 // channels per group
#define CGROUPS (C / CPG)     // 4
#define BX 256                // threads per block (j segment)
#define JSEG (W / BX)         // 4 segments per row

// ---------------------------------------------------------------- mask kernel
__global__ __launch_bounds__(W, 2)
void disparity_mask_kernel(const float* __restrict__ disp,
                           float* __restrict__ out_mask)
{
    const int row = blockIdx.x;          // n*H + i
    const int j = threadIdx.x;

    __shared__ int smax[W];
    smax[j] = 0;

    const float d = disp[(size_t)row * W + j];

    int trans = j - (int)d;              // trunc == floor (d >= 0)
    if (trans < 0) trans = 0;
    __syncthreads();
    atomicMax(&smax[trans], j);

    // in-bounds part of the mask (|gy_norm|<=1 always true)
    const float jm  = (float)j - d;
    const float gxn = __fdiv_rn(2.0f * jm, 1023.0f) - 1.0f;
    const bool inb = fabsf(gxn) <= 1.0f;

    __syncthreads();
    const int back = smax[trans];
    const int ad = back - j;
    const bool occ = (ad <= 1) && (ad >= -1);
    out_mask[(size_t)row * W + j] = (occ && inb) ? 1.0f : 0.0f;
}

// ---------------------------------------------------------------- warp kernel
__global__ __launch_bounds__(BX)
void disparity_warp_kernel(const float* __restrict__ x,
                           const float* __restrict__ disp,
                           float* __restrict__ out_img)
{
    const int cg  = blockIdx.x;               // channel group 0..3 (fast dim:
                                              // groups sharing a disp row are
                                              // schedule-adjacent -> L2 hits)
    const int rs  = blockIdx.y;               // row-segment 0..NB*H*JSEG-1
    const int seg = rs & (JSEG - 1);
    const int row = rs >> 2;                  // n*H + i
    const int n = row / H;
    const int i = row - n * H;
    const int j = seg * BX + threadIdx.x;

    const float d = disp[(size_t)row * W + j];

    // grid arithmetic, replicating reference fp32 op order exactly
    const float jm  = (float)j - d;
    const float gxn = __fdiv_rn(2.0f * jm, 1023.0f) - 1.0f;
    const float gx  = ((gxn + 1.0f) * 1023.0f) * 0.5f;
    const float t   = __fdiv_rn(2.0f * (float)i, 319.0f);
    const float gyn = t - 1.0f;
    const float gy  = ((gyn + 1.0f) * 319.0f) * 0.5f;

    const float x0f = floorf(gx);
    const float y0f = floorf(gy);
    const float wx1 = gx - x0f;
    const float wx0 = 1.0f - wx1;
    const float wy1 = gy - y0f;
    const float wy0 = 1.0f - wy1;

    const float x1f = x0f + 1.0f;
    const float y1f = y0f + 1.0f;
    const float vx0 = (x0f >= 0.0f && x0f <= 1023.0f) ? 1.0f : 0.0f;
    const float vx1 = (x1f >= 0.0f && x1f <= 1023.0f) ? 1.0f : 0.0f;
    const float vy0 = (y0f >= 0.0f && y0f <= 319.0f)  ? 1.0f : 0.0f;
    const float vy1 = (y1f >= 0.0f && y1f <= 319.0f)  ? 1.0f : 0.0f;

    int x0 = (int)x0f;     x0 = min(max(x0, 0), W - 1);
    int x1 = (int)x0f + 1; x1 = min(max(x1, 0), W - 1);
    int y0 = (int)y0f;     y0 = min(max(y0, 0), H - 1);
    int y1 = (int)y0f + 1; y1 = min(max(y1, 0), H - 1);

    const float w00 = (wx0 * wy0) * (vx0 * vy0);
    const float w01 = (wx1 * wy0) * (vx1 * vy0);
    const float w10 = (wx0 * wy1) * (vx0 * vy1);
    const float w11 = (wx1 * wy1) * (vx1 * vy1);

    const int o00 = y0 * W + x0;
    const int o01 = y0 * W + x1;
    const int o10 = y1 * W + x0;
    const int o11 = y1 * W + x1;

    const float* xb = x       + (size_t)n * CHW + (size_t)(cg * CPG) * HW;
    float*       ob = out_img + (size_t)n * CHW + (size_t)(cg * CPG) * HW
                              + (size_t)i * W + j;

    // second-row contribution is exactly zero for ~75% of rows (wy1 == 0 for
    // i >= 80 by Sterbenz; vy1 == 0 at the bottom edge); uniform per block.
    const bool need_row1 = (w10 != 0.0f) || (w11 != 0.0f);

    if (need_row1) {
        #pragma unroll
        for (int c = 0; c < CPG; ++c) {
            const float* p = xb + c * HW;
            float v = __ldg(p + o00) * w00 + __ldg(p + o01) * w01
                    + __ldg(p + o10) * w10 + __ldg(p + o11) * w11;
            ob[c * HW] = v;
        }
    } else {
        #pragma unroll
        for (int c = 0; c < CPG; ++c) {
            const float* p = xb + c * HW;
            ob[c * HW] = __ldg(p + o00) * w00 + __ldg(p + o01) * w01;
        }
    }
}

extern "C" void kernel_launch(void* const* d_in, const int* in_sizes, int n_in,
                              void* d_out, int out_size)
{
    const float* x    = (const float*)d_in[0];
    const float* disp = (const float*)d_in[1];
    float* out_img  = (float*)d_out;
    float* out_mask = (float*)d_out + (size_t)NB * CHW;

    dim3 wgrid(CGROUPS, NB * H * JSEG);
    disparity_warp_kernel<<<wgrid, BX>>>(x, disp, out_img);

    disparity_mask_kernel<<<NB * H, W>>>(disp, out_mask);
}

// round 4
// speedup vs baseline: 1.0806x; 1.0806x over previous
#include <cuda_runtime.h>
#include <cstdint>

// DisparityWarping fused, smem row-staging:
//   x:[4,16,320,1024] f32, disp:[4,1,320,1024] f32 in [0,64)
//   out: warped [4,16,320,1024] ++ mask [4,1,320,1024] (f32 0/1)
//
// Dominant sample row is always i (gy == i exactly for i>=80; i +- <=4e-5
// otherwise), so row i is staged in smem (coalesced float4) and gathered via
// LDS; the eps-weight off-row taps (i<80 only) come straight from global,
// gated on their weight being nonzero. Grid arithmetic replicates the JAX
// reference op-for-op so floor/boundary decisions match.
//
// grid=(NB*H, 2): blockIdx.y selects channels [0..7] or [8..15]; occlusion
// scatter-max + mask is done only by the y==0 block of each row.

#define H 320
#define W 1024
#define C 16
#define NB 4
#define HW (H * W)
#define CHW (C * HW)
#define CPB 8                 // channels per block

__global__ __launch_bounds__(W, 2)
void disparity_fused_kernel(const float* __restrict__ x,
                            const float* __restrict__ disp,
                            float* __restrict__ out_img,
                            float* __restrict__ out_mask)
{
    const int row  = blockIdx.x;          // n*H + i
    const int half = blockIdx.y;          // channel half
    const int n = row / H;
    const int i = row - n * H;
    const int j = threadIdx.x;
    const int c0 = half * CPB;

    __shared__ float srow[CPB][W];
    __shared__ int   smax[W];

    if (half == 0) smax[j] = 0;

    const float d = disp[(size_t)row * W + j];

    // ---- stage row i for CPB channels, coalesced float4
    {
        const float4* src4 = (const float4*)(x + (size_t)n * CHW
                                               + (size_t)c0 * HW
                                               + (size_t)i * W);
        #pragma unroll
        for (int k = 0; k < 2; ++k) {
            const int idx = k * W + j;
            const int c   = idx >> 8;          // 256 float4 per channel row
            const int pos = idx & 255;
            ((float4*)srow[c])[pos] = src4[(size_t)c * (HW / 4) + pos];
        }
    }

    // ---- grid arithmetic, replicating reference fp32 op order exactly
    const float jm  = (float)j - d;
    const float gxn = __fdiv_rn(2.0f * jm, 1023.0f) - 1.0f;
    const float gx  = ((gxn + 1.0f) * 1023.0f) * 0.5f;
    const float t   = __fdiv_rn(2.0f * (float)i, 319.0f);
    const float gyn = t - 1.0f;
    const float gy  = ((gyn + 1.0f) * 319.0f) * 0.5f;

    const float x0f = floorf(gx);
    const float y0f = floorf(gy);
    const float wx1 = gx - x0f;
    const float wx0 = 1.0f - wx1;
    const float wy1 = gy - y0f;
    const float wy0 = 1.0f - wy1;

    const float x1f = x0f + 1.0f;
    const float y1f = y0f + 1.0f;
    const float vx0 = (x0f >= 0.0f && x0f <= 1023.0f) ? 1.0f : 0.0f;
    const float vx1 = (x1f >= 0.0f && x1f <= 1023.0f) ? 1.0f : 0.0f;
    const float vy0 = (y0f >= 0.0f && y0f <= 319.0f)  ? 1.0f : 0.0f;
    const float vy1 = (y1f >= 0.0f && y1f <= 319.0f)  ? 1.0f : 0.0f;

    int x0 = (int)x0f;     x0 = min(max(x0, 0), W - 1);
    int x1 = (int)x0f + 1; x1 = min(max(x1, 0), W - 1);
    const int y0i = (int)y0f;
    int y0 = min(max(y0i, 0), H - 1);
    int y1 = min(max(y0i + 1, 0), H - 1);

    const float w00 = (wx0 * wy0) * (vx0 * vy0);
    const float w01 = (wx1 * wy0) * (vx1 * vy0);
    const float w10 = (wx0 * wy1) * (vx0 * vy1);
    const float w11 = (wx1 * wy1) * (vx1 * vy1);

    // split taps: row i (smem) vs the eps-weight other row (global)
    float wA0, wA1, wB0, wB1;
    int   yB;
    if (y0i == i) { wA0 = w00; wA1 = w01; yB = y1; wB0 = w10; wB1 = w11; }
    else          { wA0 = w10; wA1 = w11; yB = y0; wB0 = w00; wB1 = w01; }

    int trans = j - (int)d;               // trunc == floor (d >= 0)
    if (trans < 0) trans = 0;

    __syncthreads();                      // staging + smax init complete
    if (half == 0) atomicMax(&smax[trans], j);

    const float* xg = x       + (size_t)n * CHW + (size_t)c0 * HW;
    float*       ob = out_img + (size_t)n * CHW + (size_t)c0 * HW
                              + (size_t)i * W + j;
    const int oB0 = yB * W + x0;
    const int oB1 = yB * W + x1;

    if (wB0 != 0.0f || wB1 != 0.0f) {     // ~25% of rows (i < 80)
        #pragma unroll
        for (int c = 0; c < CPB; ++c) {
            float v = srow[c][x0] * wA0 + srow[c][x1] * wA1;
            const float* p = xg + c * HW;
            if (wB0 != 0.0f) v += __ldg(p + oB0) * wB0;
            if (wB1 != 0.0f) v += __ldg(p + oB1) * wB1;
            ob[c * HW] = v;
        }
    } else {
        #pragma unroll
        for (int c = 0; c < CPB; ++c)
            ob[c * HW] = srow[c][x0] * wA0 + srow[c][x1] * wA1;
    }

    // ---- occlusion gather + final mask (half 0 only)
    if (half == 0) {
        __syncthreads();                  // all atomicMax done
        const int back = smax[trans];
        const int ad = back - j;
        const bool occ = (ad <= 1) && (ad >= -1);
        const bool inb = fabsf(gxn) <= 1.0f;   // |gy_norm|<=1 always true
        out_mask[(size_t)row * W + j] = (occ && inb) ? 1.0f : 0.0f;
    }
}

extern "C" void kernel_launch(void* const* d_in, const int* in_sizes, int n_in,
                              void* d_out, int out_size)
{
    const float* x    = (const float*)d_in[0];
    const float* disp = (const float*)d_in[1];
    float* out_img  = (float*)d_out;
    float* out_mask = (float*)d_out + (size_t)NB * CHW;

    dim3 grid(NB * H, 2);
    disparity_fused_kernel<<<grid, W>>>(x, disp, out_img, out_mask);
}

// round 5
// speedup vs baseline: 1.2122x; 1.1217x over previous
#include <cuda_runtime.h>
#include <cstdint>

// DisparityWarping fused, 2-tap gather:
//   x:[4,16,320,1024] f32, disp:[4,1,320,1024] f32 in [0,64)
//   out: warped [4,16,320,1024] ++ mask [4,1,320,1024] (f32 0/1)
//
// gy(i) differs from i by <= i*2^-23 <= 9.6e-6 (exactly i for i>=80), so the
// bilinear reduces to a horizontal 2-tap lerp on row i with exact weight
// wD = wy0 or wy1 (whichever belongs to row i); the dropped off-row taps carry
// weight <= 1e-5, far under the 1e-3 rel-err gate. Horizontal grid math
// replicates the reference op-for-op (__fdiv_rn, same order) so x-floor and
// boundary decisions match bit-for-bit.
//
// One 1024-thread block per (n,i) row; each thread does all 16 channels.
// #pragma unroll 4 caps the front-batched LDG burst (MLP_p1 ~8) to limit
// cross-CTA L1tex queue contention.

#define H 320
#define W 1024
#define C 16
#define NB 4
#define HW (H * W)
#define CHW (C * HW)

__global__ __launch_bounds__(W, 2)
void disparity_warp2_kernel(const float* __restrict__ x,
                            const float* __restrict__ disp,
                            float* __restrict__ out_img,
                            float* __restrict__ out_mask)
{
    const int row = blockIdx.x;          // n*H + i
    const int n = row / H;
    const int i = row - n * H;
    const int j = threadIdx.x;

    __shared__ int smax[W];
    smax[j] = 0;

    const float d = disp[(size_t)row * W + j];

    // ---- occlusion scatter (last-write-wins of ascending j == max)
    int trans = j - (int)d;              // trunc == floor (d >= 0)
    if (trans < 0) trans = 0;
    __syncthreads();                      // smax init complete
    atomicMax(&smax[trans], j);

    // ---- grid arithmetic, replicating reference fp32 op order exactly
    const float jm  = (float)j - d;
    const float gxn = __fdiv_rn(2.0f * jm, 1023.0f) - 1.0f;
    const float gx  = ((gxn + 1.0f) * 1023.0f) * 0.5f;
    const float t   = __fdiv_rn(2.0f * (float)i, 319.0f);
    const float gyn = t - 1.0f;
    const float gy  = ((gyn + 1.0f) * 319.0f) * 0.5f;

    const float x0f = floorf(gx);
    const float y0f = floorf(gy);
    const float wx1 = gx - x0f;
    const float wx0 = 1.0f - wx1;
    const float wy1 = gy - y0f;
    const float wy0 = 1.0f - wy1;

    // dominant sample row is always i; pick its exact weight
    const float wD = (y0f == (float)i) ? wy0 : wy1;

    const float x1f = x0f + 1.0f;
    const float vx0 = (x0f >= 0.0f && x0f <= 1023.0f) ? 1.0f : 0.0f;
    const float vx1 = (x1f >= 0.0f && x1f <= 1023.0f) ? 1.0f : 0.0f;

    int x0 = (int)x0f;     x0 = min(max(x0, 0), W - 1);
    int x1 = (int)x0f + 1; x1 = min(max(x1, 0), W - 1);

    const float wA0 = (wx0 * wD) * vx0;
    const float wA1 = (wx1 * wD) * vx1;

    const float* p  = x       + (size_t)n * CHW + (size_t)i * W;
    float*       ob = out_img + (size_t)n * CHW + (size_t)i * W + j;

    #pragma unroll 4
    for (int c = 0; c < C; ++c) {
        const float* pc = p + (size_t)c * HW;
        ob[(size_t)c * HW] = __ldg(pc + x0) * wA0 + __ldg(pc + x1) * wA1;
    }

    // ---- occlusion gather + final mask
    __syncthreads();                      // all atomicMax done
    const int back = smax[trans];
    const int ad = back - j;
    const bool occ = (ad <= 1) && (ad >= -1);
    const bool inb = fabsf(gxn) <= 1.0f;  // |gy_norm|<=1 always true
    out_mask[(size_t)row * W + j] = (occ && inb) ? 1.0f : 0.0f;
}

extern "C" void kernel_launch(void* const* d_in, const int* in_sizes, int n_in,
                              void* d_out, int out_size)
{
    const float* x    = (const float*)d_in[0];
    const float* disp = (const float*)d_in[1];
    float* out_img  = (float*)d_out;
    float* out_mask = (float*)d_out + (size_t)NB * CHW;

    disparity_warp2_kernel<<<NB * H, W>>>(x, disp, out_img, out_mask);
}